// round 11
// baseline (speedup 1.0000x reference)
#include <cuda_runtime.h>
#include <cuda_fp16.h>
#include <cstdint>
#include <math.h>

#define BROWS 32768
#define DDIM  512
#define FDIM  512

#define BM 128
#define BN 128
#define BK 32
#define NKC (DDIM / BK)     // 16 k-chunks
#define STAGES 6
#define GTHREADS 256        // 8 warps, 2x4 grid, 64x32 warp tiles

// ---- scratch: W as fp16 (x converted in-GEMM via register staging) ----
__device__ __half g_w[FDIM * DDIM];

// ---- SMEM layout (bytes, dynamic) ----
// [0,512) a[] 128 floats, [512,1024) b[] 128 floats
// stages at 1024, 16 KB each: A(8K: 128 rows x 64B) B(8K: 128 rows x 64B)
#define SM_STAGE0   1024
#define STAGE_BYTES 16384
#define T_A 0
#define T_B 8192
#define SMEM_TOTAL (SM_STAGE0 + STAGES * STAGE_BYTES)   // 99328 B -> 2 CTAs/SM

__device__ __forceinline__ uint32_t s2u(const void* p) {
    uint32_t a;
    asm("{ .reg .u64 t; cvta.to.shared.u64 t, %1; cvt.u32.u64 %0, t; }" : "=r"(a) : "l"(p));
    return a;
}

// 64B rows (32 fp16), XOR swizzle: conflict-free for ldmatrix 8-row phases (R5-proven).
__device__ __forceinline__ uint32_t swz(int row, int c16) {
    return (uint32_t)(row * 64 + ((c16 ^ ((row >> 1) & 3)) << 4));
}

__device__ __forceinline__ void cp_async16(uint32_t saddr, const void* gptr) {
    asm volatile("cp.async.cg.shared.global [%0], [%1], 16;" :: "r"(saddr), "l"(gptr));
}
#define CP_COMMIT() asm volatile("cp.async.commit_group;" ::: "memory")
#define CP_WAIT5()  asm volatile("cp.async.wait_group 5;" ::: "memory")

__device__ __forceinline__ void ldsm4(uint32_t addr, uint32_t* r) {
    asm volatile("ldmatrix.sync.aligned.m8n8.x4.shared.b16 {%0,%1,%2,%3}, [%4];"
                 : "=r"(r[0]), "=r"(r[1]), "=r"(r[2]), "=r"(r[3]) : "r"(addr));
}

__device__ __forceinline__ void mma_f16(float* c, const uint32_t* a, const uint32_t* b) {
    asm volatile(
        "mma.sync.aligned.m16n8k16.row.col.f32.f16.f16.f32 "
        "{%0,%1,%2,%3}, {%4,%5,%6,%7}, {%8,%9}, {%0,%1,%2,%3};"
        : "+f"(c[0]), "+f"(c[1]), "+f"(c[2]), "+f"(c[3])
        : "r"(a[0]), "r"(a[1]), "r"(a[2]), "r"(a[3]), "r"(b[0]), "r"(b[1]));
}

__device__ __forceinline__ uint32_t pack_h2(float x, float y) {
    __half h0 = __float2half_rn(x);
    __half h1 = __float2half_rn(y);
    return ((uint32_t)__half_as_ushort(h1) << 16) | __half_as_ushort(h0);
}

// ---------------- fp32 -> fp16 convert for W only (tiny) ----------------
#define WN8 (FDIM * DDIM / 8)   // 32768 units of 8 floats

__global__ void __launch_bounds__(256) convert_w(const float* __restrict__ W) {
    size_t i = (size_t)blockIdx.x * blockDim.x + threadIdx.x;
    float4 v0 = reinterpret_cast<const float4*>(W)[i * 2];
    float4 v1 = reinterpret_cast<const float4*>(W)[i * 2 + 1];
    uint4 hp;
    hp.x = pack_h2(v0.x, v0.y);
    hp.y = pack_h2(v0.z, v0.w);
    hp.z = pack_h2(v1.x, v1.y);
    hp.w = pack_h2(v1.z, v1.w);
    reinterpret_cast<uint4*>(g_w)[i] = hp;
}

// ---------------- GEMM with register-staged A conversion ----------------
// A-chunk = 128 rows x 32 fp32 cols (16 KB). Each thread stages one 64B half-row:
//   row = tid>>1, half = tid&1 -> 16 floats = 4x float4 in registers.
__device__ __forceinline__ void ldg_a(const float* __restrict__ x, int m0, int kc,
                                      int tid, float4* st) {
    const float4* gp = reinterpret_cast<const float4*>(
        x + (size_t)(m0 + (tid >> 1)) * DDIM + kc * BK + (tid & 1) * 16);
    st[0] = gp[0];
    st[1] = gp[1];
    st[2] = gp[2];
    st[3] = gp[3];
}

__device__ __forceinline__ void sts_a(uint32_t stage_base, int tid, const float4* st) {
    int row = tid >> 1;
    int cbase = (tid & 1) * 2;   // this thread covers c16 = cbase, cbase+1
    uint4 p0, p1;
    p0.x = pack_h2(st[0].x, st[0].y);
    p0.y = pack_h2(st[0].z, st[0].w);
    p0.z = pack_h2(st[1].x, st[1].y);
    p0.w = pack_h2(st[1].z, st[1].w);
    p1.x = pack_h2(st[2].x, st[2].y);
    p1.y = pack_h2(st[2].z, st[2].w);
    p1.z = pack_h2(st[3].x, st[3].y);
    p1.w = pack_h2(st[3].z, st[3].w);
    asm volatile("st.shared.v4.b32 [%0], {%1,%2,%3,%4};"
                 :: "r"(stage_base + T_A + swz(row, cbase)),
                    "r"(p0.x), "r"(p0.y), "r"(p0.z), "r"(p0.w) : "memory");
    asm volatile("st.shared.v4.b32 [%0], {%1,%2,%3,%4};"
                 :: "r"(stage_base + T_A + swz(row, cbase + 1)),
                    "r"(p1.x), "r"(p1.y), "r"(p1.z), "r"(p1.w) : "memory");
}

__device__ __forceinline__ void load_b(uint32_t stage_base, int n0, int kc, int tid) {
    // B: 128 rows x 4 c16-chunks -> 512 chunks, 2 per thread
#pragma unroll
    for (int q = tid; q < 512; q += 256) {
        int r = q >> 2, c = q & 3;
        size_t gw = (size_t)(n0 + r) * DDIM + (size_t)kc * BK + c * 8;
        cp_async16(stage_base + T_B + swz(r, c), g_w + gw);
    }
}

__global__ void __launch_bounds__(GTHREADS, 2)
rank_activation_gemm(const float* __restrict__ x,
                     const float* __restrict__ av, const float* __restrict__ bv,
                     float* __restrict__ out) {
    extern __shared__ char smem[];
    uint32_t sm = s2u(smem);
    int tid = threadIdx.x;
    int wid = tid >> 5;
    int l = tid & 31;
    int wm = wid >> 2;   // 0..1, 64 rows each
    int wn = wid & 3;    // 0..3, 32 cols each

    // N-major inner order: 4 consecutive CTAs share the same x (A) tile in L2
    int m0 = (int)(blockIdx.x >> 2) * BM;
    int n0 = (int)(blockIdx.x & 3) * BN;

    if (tid < 128) {
        ((float*)smem)[tid]       = av[n0 + tid];
        ((float*)smem)[128 + tid] = bv[n0 + tid];
    }

    // per-lane ldmatrix offsets: s = k16 step within BK=32 chunk (0..1)
    int g = l >> 3;
    uint32_t a_sw[4][2], b_sw[2][2];
#pragma unroll
    for (int mt = 0; mt < 4; mt++) {
        int row = wm * 64 + mt * 16 + ((g & 1) << 3) + (l & 7);
#pragma unroll
        for (int s = 0; s < 2; s++) a_sw[mt][s] = swz(row, s * 2 + (g >> 1));
    }
#pragma unroll
    for (int t = 0; t < 2; t++) {
        int row = wn * 32 + t * 16 + ((g >> 1) << 3) + (l & 7);
#pragma unroll
        for (int s = 0; s < 2; s++) b_sw[t][s] = swz(row, s * 2 + (g & 1));
    }

    float acc[4][4][4];
#pragma unroll
    for (int i = 0; i < 4; i++)
#pragma unroll
        for (int j = 0; j < 4; j++)
#pragma unroll
            for (int k = 0; k < 4; k++) acc[i][j][k] = 0.0f;

    float4 stg[4];   // register staging: A fp32 for one future chunk

    // ---- prologue ----
    // A(0): load + store (one exposed LDG stall, once)
    ldg_a(x, m0, 0, tid, stg);
    sts_a(sm + SM_STAGE0 + 0 * STAGE_BYTES, tid, stg);
    // A(1): load, hold in regs (STS'd at top of chunk 0)
    ldg_a(x, m0, 1, tid, stg);
    // B(0..4): cp.async, one group each
#pragma unroll
    for (int p = 0; p < STAGES - 1; p++) {
        load_b(sm + SM_STAGE0 + p * STAGE_BYTES, n0, p, tid);
        CP_COMMIT();
    }

    for (int kc = 0; kc < NKC; kc++) {
        // STS held A regs (data for chunk kc+1) into its stage
        if (kc + 1 < NKC)
            sts_a(sm + SM_STAGE0 + ((kc + 1) % STAGES) * STAGE_BYTES, tid, stg);
        // LDG A for chunk kc+2 (latency covered by this chunk's MMAs)
        if (kc + 2 < NKC)
            ldg_a(x, m0, kc + 2, tid, stg);
        // B for chunk kc+5
        if (kc + STAGES - 1 < NKC)
            load_b(sm + SM_STAGE0 + ((kc + STAGES - 1) % STAGES) * STAGE_BYTES,
                   n0, kc + STAGES - 1, tid);
        CP_COMMIT();   // uniform group accounting

        CP_WAIT5();    // B group for chunk kc complete
        __syncthreads();   // all warps' A STS for kc (done at kc-1) + B visible

        uint32_t st = sm + SM_STAGE0 + (kc % STAGES) * STAGE_BYTES;
#pragma unroll
        for (int s = 0; s < 2; s++) {   // two k16 steps per 32-chunk
            uint32_t A[4][4], B[2][4];
#pragma unroll
            for (int t = 0; t < 2; t++) ldsm4(st + T_B + b_sw[t][s], B[t]);
#pragma unroll
            for (int mt = 0; mt < 4; mt++) ldsm4(st + T_A + a_sw[mt][s], A[mt]);
#pragma unroll
            for (int mt = 0; mt < 4; mt++) {
#pragma unroll
                for (int nt = 0; nt < 4; nt++) {
                    const uint32_t* bf = &B[nt >> 1][(nt & 1) * 2];
                    mma_f16(acc[mt][nt], A[mt], bf);
                }
            }
        }
    }

    // epilogue: out = tanh(a*z + b)
    const float* sA = (const float*)smem;
    const float* sB = (const float*)smem + 128;
#pragma unroll
    for (int mt = 0; mt < 4; mt++) {
        int row = m0 + wm * 64 + mt * 16 + (l >> 2);
#pragma unroll
        for (int nt = 0; nt < 4; nt++) {
            int cl = wn * 32 + nt * 8 + 2 * (l & 3);
            float a0 = sA[cl], a1 = sA[cl + 1];
            float b0 = sB[cl], b1 = sB[cl + 1];
            float2 v0, v1;
            v0.x = tanhf(fmaf(a0, acc[mt][nt][0], b0));
            v0.y = tanhf(fmaf(a1, acc[mt][nt][1], b1));
            v1.x = tanhf(fmaf(a0, acc[mt][nt][2], b0));
            v1.y = tanhf(fmaf(a1, acc[mt][nt][3], b1));
            *reinterpret_cast<float2*>(out + (size_t)row * FDIM + n0 + cl) = v0;
            *reinterpret_cast<float2*>(out + (size_t)(row + 8) * FDIM + n0 + cl) = v1;
        }
    }
}

extern "C" void kernel_launch(void* const* d_in, const int* in_sizes, int n_in,
                              void* d_out, int out_size) {
    const float* x = (const float*)d_in[0];
    const float* W = (const float*)d_in[1];
    const float* a = (const float*)d_in[2];
    const float* b = (const float*)d_in[3];
    float* out = (float*)d_out;

    convert_w<<<WN8 / 256, 256>>>(W);

    cudaFuncSetAttribute(rank_activation_gemm,
                         cudaFuncAttributeMaxDynamicSharedMemorySize, SMEM_TOTAL);
    dim3 grid((BROWS / BM) * (FDIM / BN));   // 256 * 4 = 1024
    rank_activation_gemm<<<grid, GTHREADS, SMEM_TOTAL>>>(x, a, b, out);
}

// round 12
// speedup vs baseline: 1.2133x; 1.2133x over previous
#include <cuda_runtime.h>
#include <cuda_fp16.h>
#include <cstdint>
#include <math.h>

#define BROWS 32768
#define DDIM  512
#define FDIM  512

#define BM 128
#define BN 128
#define BK 64
#define NKC (DDIM / BK)     // 8 k-chunks
#define STAGES 3
#define GTHREADS 256        // 8 warps, 2x4 grid, 64x32 warp tiles

// ---- scratch: x and W as fp16 ----
__device__ __half g_x[BROWS * DDIM];
__device__ __half g_w[FDIM * DDIM];

// ---- SMEM layout (bytes, dynamic) ----
// [0,512) a[] 128 floats, [512,1024) b[] 128 floats
// stages at 1024, 32 KB each: A(16K: 128 rows x 128B) B(16K: 128 rows x 128B)
#define SM_STAGE0   1024
#define STAGE_BYTES 32768
#define T_A 0
#define T_B 16384
#define SMEM_TOTAL (SM_STAGE0 + STAGES * STAGE_BYTES)   // 99328 B -> 2 CTAs/SM

__device__ __forceinline__ uint32_t s2u(const void* p) {
    uint32_t a;
    asm("{ .reg .u64 t; cvta.to.shared.u64 t, %1; cvt.u32.u64 %0, t; }" : "=r"(a) : "l"(p));
    return a;
}

// 128B rows (64 fp16), 8-way XOR swizzle on 16B chunks: conflict-free for
// ldmatrix (8 consecutive rows, same c16 -> 8 distinct chunk-banks).
__device__ __forceinline__ uint32_t swz64(int row, int c16) {
    return (uint32_t)(row * 128 + ((c16 ^ (row & 7)) << 4));
}

__device__ __forceinline__ void cp_async16(uint32_t saddr, const void* gptr) {
    asm volatile("cp.async.cg.shared.global [%0], [%1], 16;" :: "r"(saddr), "l"(gptr));
}
#define CP_COMMIT() asm volatile("cp.async.commit_group;" ::: "memory")
#define CP_WAIT1()  asm volatile("cp.async.wait_group 1;" ::: "memory")

__device__ __forceinline__ void ldsm4(uint32_t addr, uint32_t* r) {
    asm volatile("ldmatrix.sync.aligned.m8n8.x4.shared.b16 {%0,%1,%2,%3}, [%4];"
                 : "=r"(r[0]), "=r"(r[1]), "=r"(r[2]), "=r"(r[3]) : "r"(addr));
}

__device__ __forceinline__ void mma_f16(float* c, const uint32_t* a, const uint32_t* b) {
    asm volatile(
        "mma.sync.aligned.m16n8k16.row.col.f32.f16.f16.f32 "
        "{%0,%1,%2,%3}, {%4,%5,%6,%7}, {%8,%9}, {%0,%1,%2,%3};"
        : "+f"(c[0]), "+f"(c[1]), "+f"(c[2]), "+f"(c[3])
        : "r"(a[0]), "r"(a[1]), "r"(a[2]), "r"(a[3]), "r"(b[0]), "r"(b[1]));
}

__device__ __forceinline__ uint32_t pack_h2(float x, float y) {
    __half h0 = __float2half_rn(x);
    __half h1 = __float2half_rn(y);
    return ((uint32_t)__half_as_ushort(h1) << 16) | __half_as_ushort(h0);
}

// ---------------- fp32 -> fp16 convert (x and W), one launch, MLP=4 ----------------
#define XN8 (BROWS * DDIM / 8)                 // 2097152
#define WN8 (FDIM * DDIM / 8)                  // 32768
#define TOTN8 (XN8 + WN8)                      // 2129920
#define CONV_THREADS_TOTAL (TOTN8 / 4)         // 532480
#define CONV_BLOCKS (CONV_THREADS_TOTAL / 256) // 2080

__device__ __forceinline__ void conv8(const float* __restrict__ src, size_t i8,
                                      __half* __restrict__ dst) {
    float4 v0 = reinterpret_cast<const float4*>(src)[i8 * 2];
    float4 v1 = reinterpret_cast<const float4*>(src)[i8 * 2 + 1];
    uint4 hp;
    hp.x = pack_h2(v0.x, v0.y);
    hp.y = pack_h2(v0.z, v0.w);
    hp.z = pack_h2(v1.x, v1.y);
    hp.w = pack_h2(v1.z, v1.w);
    reinterpret_cast<uint4*>(dst)[i8] = hp;
}

__global__ void __launch_bounds__(256) convert_all(const float* __restrict__ x,
                                                   const float* __restrict__ W) {
    size_t base = (size_t)blockIdx.x * blockDim.x + threadIdx.x;
#pragma unroll
    for (int j = 0; j < 4; j++) {   // 4 independent strided units -> MLP=4+
        size_t i = base + (size_t)j * CONV_THREADS_TOTAL;
        if (i < XN8) conv8(x, i, g_x);
        else         conv8(W, i - XN8, g_w);
    }
}

// ---------------- GEMM + tanh epilogue ----------------
__device__ __forceinline__ void load_stage(uint32_t stage_base, int m0, int n0, int kc, int tid) {
    // A: 128 rows x 8 c16-chunks -> 1024 chunks, 4 per thread
#pragma unroll
    for (int q = tid; q < 1024; q += 256) {
        int r = q >> 3, c = q & 7;
        uint32_t soff = swz64(r, c);
        size_t gx = (size_t)(m0 + r) * DDIM + (size_t)kc * BK + c * 8;
        cp_async16(stage_base + T_A + soff, g_x + gx);
    }
    // B: 128 rows x 8 chunks -> 1024 chunks, 4 per thread
#pragma unroll
    for (int q = tid; q < 1024; q += 256) {
        int r = q >> 3, c = q & 7;
        uint32_t soff = swz64(r, c);
        size_t gw = (size_t)(n0 + r) * DDIM + (size_t)kc * BK + c * 8;
        cp_async16(stage_base + T_B + soff, g_w + gw);
    }
}

__global__ void __launch_bounds__(GTHREADS, 2)
rank_activation_gemm(const float* __restrict__ av, const float* __restrict__ bv,
                     float* __restrict__ out) {
    extern __shared__ char smem[];
    uint32_t sm = s2u(smem);
    int tid = threadIdx.x;
    int wid = tid >> 5;
    int l = tid & 31;
    int wm = wid >> 2;   // 0..1, 64 rows each
    int wn = wid & 3;    // 0..3, 32 cols each

    // N-major inner order: 4 consecutive CTAs share the same x (A) tile in L2
    int m0 = (int)(blockIdx.x >> 2) * BM;
    int n0 = (int)(blockIdx.x & 3) * BN;

    if (tid < 128) {
        ((float*)smem)[tid]       = av[n0 + tid];
        ((float*)smem)[128 + tid] = bv[n0 + tid];
    }

    // Per-warp k-step permutation: warp w executes steps in order (si + so) & 3.
    // Breaks the cross-warp LDSM/MMA phase lock after each chunk barrier.
    int so = wid & 3;

    // per-lane ldmatrix offsets, PRE-PERMUTED: index si (compile-time) holds
    // the address for actual step s = (si + so) & 3.
    int g = l >> 3;
    uint32_t a_sw[4][4], b_sw[2][4];
#pragma unroll
    for (int mt = 0; mt < 4; mt++) {
        int row = wm * 64 + mt * 16 + ((g & 1) << 3) + (l & 7);
#pragma unroll
        for (int si = 0; si < 4; si++) {
            int s = (si + so) & 3;
            a_sw[mt][si] = swz64(row, s * 2 + (g >> 1));
        }
    }
#pragma unroll
    for (int t = 0; t < 2; t++) {
        int row = wn * 32 + t * 16 + ((g >> 1) << 3) + (l & 7);
#pragma unroll
        for (int si = 0; si < 4; si++) {
            int s = (si + so) & 3;
            b_sw[t][si] = swz64(row, s * 2 + (g & 1));
        }
    }

    float acc[4][4][4];
#pragma unroll
    for (int i = 0; i < 4; i++)
#pragma unroll
        for (int j = 0; j < 4; j++)
#pragma unroll
            for (int k = 0; k < 4; k++) acc[i][j][k] = 0.0f;

    // prologue: stages 0,1
    load_stage(sm + SM_STAGE0, m0, n0, 0, tid);
    CP_COMMIT();
    load_stage(sm + SM_STAGE0 + STAGE_BYTES, m0, n0, 1, tid);
    CP_COMMIT();

    for (int kc = 0; kc < NKC; kc++) {
        CP_WAIT1();
        __syncthreads();

        if (kc + 2 < NKC)
            load_stage(sm + SM_STAGE0 + ((kc + 2) % STAGES) * STAGE_BYTES, m0, n0, kc + 2, tid);
        CP_COMMIT();   // uniform group accounting

        uint32_t st = sm + SM_STAGE0 + (kc % STAGES) * STAGE_BYTES;
#pragma unroll
        for (int si = 0; si < 4; si++) {   // four k16 steps, per-warp permuted order
            uint32_t A[4][4], B[2][4];
#pragma unroll
            for (int t = 0; t < 2; t++) ldsm4(st + T_B + b_sw[t][si], B[t]);
#pragma unroll
            for (int mt = 0; mt < 4; mt++) ldsm4(st + T_A + a_sw[mt][si], A[mt]);
#pragma unroll
            for (int mt = 0; mt < 4; mt++) {
#pragma unroll
                for (int nt = 0; nt < 4; nt++) {
                    const uint32_t* bf = &B[nt >> 1][(nt & 1) * 2];
                    mma_f16(acc[mt][nt], A[mt], bf);
                }
            }
        }
    }

    // epilogue: out = tanh(a*z + b)
    const float* sA = (const float*)smem;
    const float* sB = (const float*)smem + 128;
#pragma unroll
    for (int mt = 0; mt < 4; mt++) {
        int row = m0 + wm * 64 + mt * 16 + (l >> 2);
#pragma unroll
        for (int nt = 0; nt < 4; nt++) {
            int cl = wn * 32 + nt * 8 + 2 * (l & 3);
            float a0 = sA[cl], a1 = sA[cl + 1];
            float b0 = sB[cl], b1 = sB[cl + 1];
            float2 v0, v1;
            v0.x = tanhf(fmaf(a0, acc[mt][nt][0], b0));
            v0.y = tanhf(fmaf(a1, acc[mt][nt][1], b1));
            v1.x = tanhf(fmaf(a0, acc[mt][nt][2], b0));
            v1.y = tanhf(fmaf(a1, acc[mt][nt][3], b1));
            *reinterpret_cast<float2*>(out + (size_t)row * FDIM + n0 + cl) = v0;
            *reinterpret_cast<float2*>(out + (size_t)(row + 8) * FDIM + n0 + cl) = v1;
        }
    }
}

extern "C" void kernel_launch(void* const* d_in, const int* in_sizes, int n_in,
                              void* d_out, int out_size) {
    const float* x = (const float*)d_in[0];
    const float* W = (const float*)d_in[1];
    const float* a = (const float*)d_in[2];
    const float* b = (const float*)d_in[3];
    float* out = (float*)d_out;

    convert_all<<<CONV_BLOCKS, 256>>>(x, W);

    cudaFuncSetAttribute(rank_activation_gemm,
                         cudaFuncAttributeMaxDynamicSharedMemorySize, SMEM_TOTAL);
    dim3 grid((BROWS / BM) * (FDIM / BN));   // 256 * 4 = 1024
    rank_activation_gemm<<<grid, GTHREADS, SMEM_TOTAL>>>(a, b, out);
}

// round 13
// speedup vs baseline: 1.2214x; 1.0067x over previous
#include <cuda_runtime.h>
#include <cuda_fp16.h>
#include <cstdint>
#include <math.h>

#define BROWS 32768
#define DDIM  512
#define FDIM  512

#define BM 128
#define BN 128
#define BK 64
#define NKC (DDIM / BK)     // 8 k-chunks
#define STAGES 3
#define GTHREADS 256        // 8 warps, 2x4 grid, 64x32 warp tiles

// ---- scratch: x and W as fp16; cross-CTA generation flags ----
__device__ __half g_x[BROWS * DDIM];
__device__ __half g_w[FDIM * DDIM];
__device__ int    g_flag[BROWS / BM];   // 256 monotonic counters (zero-init once)

// ---- SMEM layout (bytes, dynamic) ----
#define SM_STAGE0   1024
#define STAGE_BYTES 32768
#define T_A 0
#define T_B 16384
#define SMEM_TOTAL (SM_STAGE0 + STAGES * STAGE_BYTES)   // 99328 B -> 2 CTAs/SM

__device__ __forceinline__ uint32_t s2u(const void* p) {
    uint32_t a;
    asm("{ .reg .u64 t; cvta.to.shared.u64 t, %1; cvt.u32.u64 %0, t; }" : "=r"(a) : "l"(p));
    return a;
}

// 128B rows (64 fp16), 8-way XOR swizzle on 16B chunks (R7/R9-proven).
__device__ __forceinline__ uint32_t swz64(int row, int c16) {
    return (uint32_t)(row * 128 + ((c16 ^ (row & 7)) << 4));
}

__device__ __forceinline__ void cp_async16(uint32_t saddr, const void* gptr) {
    asm volatile("cp.async.cg.shared.global [%0], [%1], 16;" :: "r"(saddr), "l"(gptr));
}
#define CP_COMMIT() asm volatile("cp.async.commit_group;" ::: "memory")
#define CP_WAIT1()  asm volatile("cp.async.wait_group 1;" ::: "memory")

__device__ __forceinline__ void ldsm4(uint32_t addr, uint32_t* r) {
    asm volatile("ldmatrix.sync.aligned.m8n8.x4.shared.b16 {%0,%1,%2,%3}, [%4];"
                 : "=r"(r[0]), "=r"(r[1]), "=r"(r[2]), "=r"(r[3]) : "r"(addr));
}

__device__ __forceinline__ void mma_f16(float* c, const uint32_t* a, const uint32_t* b) {
    asm volatile(
        "mma.sync.aligned.m16n8k16.row.col.f32.f16.f16.f32 "
        "{%0,%1,%2,%3}, {%4,%5,%6,%7}, {%8,%9}, {%0,%1,%2,%3};"
        : "+f"(c[0]), "+f"(c[1]), "+f"(c[2]), "+f"(c[3])
        : "r"(a[0]), "r"(a[1]), "r"(a[2]), "r"(a[3]), "r"(b[0]), "r"(b[1]));
}

__device__ __forceinline__ uint32_t pack_h2(float x, float y) {
    __half h0 = __float2half_rn(x);
    __half h1 = __float2half_rn(y);
    return ((uint32_t)__half_as_ushort(h1) << 16) | __half_as_ushort(h0);
}

// ---------------- fp32 -> fp16 convert for W only (tiny) ----------------
#define WN8 (FDIM * DDIM / 8)   // 32768 units of 8 floats

__global__ void __launch_bounds__(256) convert_w(const float* __restrict__ W) {
    size_t i = (size_t)blockIdx.x * blockDim.x + threadIdx.x;
    float4 v0 = reinterpret_cast<const float4*>(W)[i * 2];
    float4 v1 = reinterpret_cast<const float4*>(W)[i * 2 + 1];
    uint4 hp;
    hp.x = pack_h2(v0.x, v0.y);
    hp.y = pack_h2(v0.z, v0.w);
    hp.z = pack_h2(v1.x, v1.y);
    hp.w = pack_h2(v1.z, v1.w);
    reinterpret_cast<uint4*>(g_w)[i] = hp;
}

// ---------------- GEMM + in-kernel x-convert + tanh epilogue ----------------
__device__ __forceinline__ void load_stage(uint32_t stage_base, int m0, int n0, int kc, int tid) {
    // A: 128 rows x 8 c16-chunks -> 1024 chunks, 4 per thread
#pragma unroll
    for (int q = tid; q < 1024; q += 256) {
        int r = q >> 3, c = q & 7;
        uint32_t soff = swz64(r, c);
        size_t gx = (size_t)(m0 + r) * DDIM + (size_t)kc * BK + c * 8;
        cp_async16(stage_base + T_A + soff, g_x + gx);
    }
    // B: 128 rows x 8 chunks -> 1024 chunks, 4 per thread
#pragma unroll
    for (int q = tid; q < 1024; q += 256) {
        int r = q >> 3, c = q & 7;
        uint32_t soff = swz64(r, c);
        size_t gw = (size_t)(n0 + r) * DDIM + (size_t)kc * BK + c * 8;
        cp_async16(stage_base + T_B + soff, g_w + gw);
    }
}

__global__ void __launch_bounds__(GTHREADS, 2)
rank_activation_gemm(const float* __restrict__ x,
                     const float* __restrict__ av, const float* __restrict__ bv,
                     float* __restrict__ out) {
    extern __shared__ char smem[];
    uint32_t sm = s2u(smem);
    int tid = threadIdx.x;
    int wid = tid >> 5;
    int l = tid & 31;
    int wm = wid >> 2;   // 0..1, 64 rows each
    int wn = wid & 3;    // 0..3, 32 cols each

    // N-major inner order: 4 consecutive CTAs share the same x (A) tile
    int mt_idx = (int)(blockIdx.x >> 2);
    int sub    = (int)(blockIdx.x & 3);
    int m0 = mt_idx * BM;
    int n0 = sub * BN;

    // ---- Phase 1: convert this CTA's quarter of the x slab (32 contiguous rows) ----
    {
        size_t slab = (size_t)(m0 + sub * 32) * DDIM;   // contiguous 32x512 floats
        const float4* xs = reinterpret_cast<const float4*>(x + slab);
        uint4* xd = reinterpret_cast<uint4*>(g_x + slab);
#pragma unroll
        for (int q = tid; q < 2048; q += 256) {         // 2048 uint4 = 32KB fp16
            float4 v0 = xs[q * 2];
            float4 v1 = xs[q * 2 + 1];
            uint4 hp;
            hp.x = pack_h2(v0.x, v0.y);
            hp.y = pack_h2(v0.z, v0.w);
            hp.z = pack_h2(v1.x, v1.y);
            hp.w = pack_h2(v1.z, v1.w);
            xd[q] = hp;
        }
    }
    __threadfence();
    __syncthreads();

    // ---- Phase 2: generation-counter handshake (graph-replay safe) ----
    if (tid == 0) {
        int* fp = &g_flag[mt_idx];
        int old;
        asm volatile("atom.global.add.release.gpu.s32 %0, [%1], 1;"
                     : "=r"(old) : "l"(fp) : "memory");
        int target = ((old >> 2) + 1) << 2;   // all 4 quarters of my generation
        int v;
        do {
            asm volatile("ld.global.acquire.gpu.b32 %0, [%1];" : "=r"(v) : "l"(fp) : "memory");
            if (v < target) __nanosleep(64);
        } while (v < target);
    }
    __syncthreads();

    if (tid < 128) {
        ((float*)smem)[tid]       = av[n0 + tid];
        ((float*)smem)[128 + tid] = bv[n0 + tid];
    }

    // per-lane ldmatrix offsets: s = k16 step within BK=64 chunk (0..3)
    int g = l >> 3;
    uint32_t a_sw[4][4], b_sw[2][4];
#pragma unroll
    for (int mt = 0; mt < 4; mt++) {
        int row = wm * 64 + mt * 16 + ((g & 1) << 3) + (l & 7);
#pragma unroll
        for (int s = 0; s < 4; s++) a_sw[mt][s] = swz64(row, s * 2 + (g >> 1));
    }
#pragma unroll
    for (int t = 0; t < 2; t++) {
        int row = wn * 32 + t * 16 + ((g >> 1) << 3) + (l & 7);
#pragma unroll
        for (int s = 0; s < 4; s++) b_sw[t][s] = swz64(row, s * 2 + (g & 1));
    }

    float acc[4][4][4];
#pragma unroll
    for (int i = 0; i < 4; i++)
#pragma unroll
        for (int j = 0; j < 4; j++)
#pragma unroll
            for (int k = 0; k < 4; k++) acc[i][j][k] = 0.0f;

    // prologue: stages 0,1
    load_stage(sm + SM_STAGE0, m0, n0, 0, tid);
    CP_COMMIT();
    load_stage(sm + SM_STAGE0 + STAGE_BYTES, m0, n0, 1, tid);
    CP_COMMIT();

    for (int kc = 0; kc < NKC; kc++) {
        CP_WAIT1();
        __syncthreads();

        if (kc + 2 < NKC)
            load_stage(sm + SM_STAGE0 + ((kc + 2) % STAGES) * STAGE_BYTES, m0, n0, kc + 2, tid);
        CP_COMMIT();   // uniform group accounting

        uint32_t st = sm + SM_STAGE0 + (kc % STAGES) * STAGE_BYTES;
#pragma unroll
        for (int s = 0; s < 4; s++) {   // four k16 steps per 64-chunk
            uint32_t A[4][4], B[2][4];
#pragma unroll
            for (int t = 0; t < 2; t++) ldsm4(st + T_B + b_sw[t][s], B[t]);
#pragma unroll
            for (int mt = 0; mt < 4; mt++) ldsm4(st + T_A + a_sw[mt][s], A[mt]);
#pragma unroll
            for (int mt = 0; mt < 4; mt++) {
#pragma unroll
                for (int nt = 0; nt < 4; nt++) {
                    const uint32_t* bf = &B[nt >> 1][(nt & 1) * 2];
                    mma_f16(acc[mt][nt], A[mt], bf);
                }
            }
        }
    }

    // epilogue: out = tanh(a*z + b)
    const float* sA = (const float*)smem;
    const float* sB = (const float*)smem + 128;
#pragma unroll
    for (int mt = 0; mt < 4; mt++) {
        int row = m0 + wm * 64 + mt * 16 + (l >> 2);
#pragma unroll
        for (int nt = 0; nt < 4; nt++) {
            int cl = wn * 32 + nt * 8 + 2 * (l & 3);
            float a0 = sA[cl], a1 = sA[cl + 1];
            float b0 = sB[cl], b1 = sB[cl + 1];
            float2 v0, v1;
            v0.x = tanhf(fmaf(a0, acc[mt][nt][0], b0));
            v0.y = tanhf(fmaf(a1, acc[mt][nt][1], b1));
            v1.x = tanhf(fmaf(a0, acc[mt][nt][2], b0));
            v1.y = tanhf(fmaf(a1, acc[mt][nt][3], b1));
            *reinterpret_cast<float2*>(out + (size_t)row * FDIM + n0 + cl) = v0;
            *reinterpret_cast<float2*>(out + (size_t)(row + 8) * FDIM + n0 + cl) = v1;
        }
    }
}

extern "C" void kernel_launch(void* const* d_in, const int* in_sizes, int n_in,
                              void* d_out, int out_size) {
    const float* x = (const float*)d_in[0];
    const float* W = (const float*)d_in[1];
    const float* a = (const float*)d_in[2];
    const float* b = (const float*)d_in[3];
    float* out = (float*)d_out;

    convert_w<<<WN8 / 256, 256>>>(W);

    cudaFuncSetAttribute(rank_activation_gemm,
                         cudaFuncAttributeMaxDynamicSharedMemorySize, SMEM_TOTAL);
    dim3 grid((BROWS / BM) * (FDIM / BN));   // 256 * 4 = 1024
    rank_activation_gemm<<<grid, GTHREADS, SMEM_TOTAL>>>(x, a, b, out);
}